// round 9
// baseline (speedup 1.0000x reference)
#include <cuda_runtime.h>
#include <stdint.h>

#define BB 512
#define SS 1024
#define TT 48

__device__ float g_partial[BB];

__device__ __forceinline__ unsigned long long pk2(float x, float y) {
    unsigned long long r;
    asm("mov.b64 %0, {%1,%2};" : "=l"(r) : "f"(x), "f"(y));
    return r;
}
__device__ __forceinline__ void upk2(unsigned long long v, float& x, float& y) {
    asm("mov.b64 {%0,%1}, %2;" : "=f"(x), "=f"(y) : "l"(v));
}
__device__ __forceinline__ unsigned long long fma2(unsigned long long a, unsigned long long b, unsigned long long c) {
    unsigned long long d;
    asm("fma.rn.f32x2 %0, %1, %2, %3;" : "=l"(d) : "l"(a), "l"(b), "l"(c));
    return d;
}

// One warp per sequence. 4 warps/CTA (one per SMSP), 128 CTAs = 1 CTA/SM.
// Split-K matvec: lane (h=l>>4, c=l&15) computes output columns {3c,3c+1,3c+2}
// over input half [24h, 24h+24); halves combined via shfl_xor(16).
// Numerator + length: fully parallel warp prologue (no per-step divergence).
__global__ __launch_bounds__(128, 1) void crf_main(
    const float* __restrict__ em,          // [B,S,T]
    const int* __restrict__ tags,          // [B,S]
    const unsigned char* __restrict__ mask,// [B,S] bool OR int32 (auto-detected)
    const float* __restrict__ startT,      // [T]
    const float* __restrict__ endT,        // [T]
    const float* __restrict__ trans)       // [T,T]
{
    __shared__ __align__(16) float sP[4][2][TT];

    const unsigned FULL = 0xffffffffu;
    int tid = threadIdx.x;
    int w   = tid >> 5;
    int l   = tid & 31;
    int b   = blockIdx.x * 4 + w;
    int h   = l >> 4;          // input half (0: i in [0,24), 1: i in [24,48))
    int c   = l & 15;          // column group: cols 3c, 3c+1, 3c+2

    bool isbool = ((mask[1] | mask[1025] | mask[2049] | mask[3073]) != 0);

    const float* embT = em + (size_t)b * SS * TT;
    const int*   tgT  = tags + (size_t)b * SS;

    // ===== parallel prologue: gold-path numerator + length (32 t's/lane) =====
    float num = 0.f;
    int cnt = 0;
    #pragma unroll 4
    for (int k = 0; k < 32; k++) {
        int t = l + 32 * k;
        int mk = isbool ? (int)mask[(size_t)b * SS + t]
                        : ((const int*)mask)[(size_t)b * SS + t];
        int tg = tgT[t];
        if (t == 0) {
            num += startT[tg] + embT[tg];
        } else {
            int tgm = tgT[t - 1];
            float cval = trans[tgm * TT + tg] + embT[t * TT + tg];
            num += mk ? cval : 0.f;
        }
        cnt += mk ? 1 : 0;
    }
    #pragma unroll
    for (int o = 16; o; o >>= 1) {
        num += __shfl_xor_sync(FULL, num, o);
        cnt += __shfl_xor_sync(FULL, cnt, o);
    }
    int len = cnt;
    if (len < 1) len = 1;
    if (len > SS) len = SS;
    num += endT[tgT[len - 1]];          // uniform across lanes

    // ===== E columns in registers: 3 cols x 12 input-pairs (f32x2) =====
    int j0 = 3 * c;
    int i0 = 24 * h;
    unsigned long long EA[12], EB[12], EC[12];
    #pragma unroll
    for (int m = 0; m < 12; m++) {
        int ia = i0 + 2 * m, ib = ia + 1;
        EA[m] = pk2(__expf(trans[ia * TT + j0]),     __expf(trans[ib * TT + j0]));
        EB[m] = pk2(__expf(trans[ia * TT + j0 + 1]), __expf(trans[ib * TT + j0 + 1]));
        EC[m] = pk2(__expf(trans[ia * TT + j0 + 2]), __expf(trans[ib * TT + j0 + 2]));
    }

    // ===== init: p0 = exp(start + emit0 - shift), written R3-layout =====
    float sA0 = startT[l] + embT[l];
    float shift = __shfl_sync(FULL, sA0, 0);
    sP[w][0][l] = __expf(sA0 - shift);
    if (h == 0) {
        float sB0 = startT[32 + c] + embT[32 + c];
        sP[w][0][32 + c] = __expf(sB0 - shift);
    }
    __syncwarp();

    // ===== emission prefetch ring (depth 4), 3 floats per step =====
    float bx[4], by[4], bz[4];
    #pragma unroll
    for (int u = 0; u < 4; u++) {
        int tt = 1 + u;
        bx[u] = embT[tt * TT + j0];
        by[u] = embT[tt * TT + j0 + 1];
        bz[u] = embT[tt * TT + j0 + 2];
    }

    int ksum = 0, kpend = 0;
    float kf = 0.f;

    // ===== recurrence: p <- (E^T p) * exp(emit_t) * 2^-k (k lagged 2 steps) ==
    for (int t0 = 1; t0 < len; t0 += 4) {
        #pragma unroll
        for (int u = 0; u < 4; u++) {
            int t = t0 + u;
            int ph = (u + 1) & 3;          // == t & 3
            if (t < len) {
                float w0 = __expf(bx[u]);
                float w1 = __expf(by[u]);
                float w2 = __expf(bz[u]);
                if (ph == 2) {
                    kpend = (int)kf;
                    float Mf = __uint_as_float((unsigned)(127 - kpend) << 23);
                    w0 *= Mf; w1 *= Mf; w2 *= Mf;
                }

                int tp = t + 4; if (tp > SS - 1) tp = SS - 1;
                float nx = embT[tp * TT + j0];
                float ny = embT[tp * TT + j0 + 1];
                float nz = embT[tp * TT + j0 + 2];

                int rb = (t + 1) & 1, wb = t & 1;
                const ulonglong2* sp =
                    reinterpret_cast<const ulonglong2*>(&sP[w][rb][i0]);
                unsigned long long aA = 0, aB = 0, aC = 0;
                #pragma unroll
                for (int q = 0; q < 6; q++) {
                    ulonglong2 v = sp[q];
                    aA = fma2(v.x, EA[2 * q], aA);
                    aB = fma2(v.x, EB[2 * q], aB);
                    aC = fma2(v.x, EC[2 * q], aC);
                    aA = fma2(v.y, EA[2 * q + 1], aA);
                    aB = fma2(v.y, EB[2 * q + 1], aB);
                    aC = fma2(v.y, EC[2 * q + 1], aC);
                }
                float xA, yA, xB, yB, xC, yC;
                upk2(aA, xA, yA);
                upk2(aB, xB, yB);
                upk2(aC, xC, yC);
                float pA = xA + yA, pB = xB + yB, pC = xC + yC;
                pA += __shfl_xor_sync(FULL, pA, 16);
                pB += __shfl_xor_sync(FULL, pB, 16);
                pC += __shfl_xor_sync(FULL, pC, 16);
                pA *= w0; pB *= w1; pC *= w2;

                bx[u] = nx; by[u] = ny; bz[u] = nz;

                if (ph == 0) {
                    // lane 0 holds col 0; compute on all lanes, broadcast
                    unsigned eb = (__float_as_uint(pA) >> 23) & 255u;
                    if (eb < 64u) eb = 64u;
                    if (eb > 190u) eb = 190u;
                    float kz = (float)((int)eb - 127);
                    kf = __shfl_sync(FULL, kz, 0);
                } else if (ph == 2) {
                    ksum += kpend;
                }

                if (h == 0) {
                    sP[w][wb][j0]     = pA;
                    sP[w][wb][j0 + 1] = pB;
                    sP[w][wb][j0 + 2] = pC;
                }
                __syncwarp();
            }
        }
    }

    // ===== finalize: logZ = log(sum_j p_j e^{end_j}) + shift + ksum*ln2 =====
    int fb = (len - 1) & 1;
    float fin = 0.f;
    if (h == 0) {
        fin = sP[w][fb][j0]     * __expf(endT[j0])
            + sP[w][fb][j0 + 1] * __expf(endT[j0 + 1])
            + sP[w][fb][j0 + 2] * __expf(endT[j0 + 2]);
    }
    #pragma unroll
    for (int o = 16; o; o >>= 1) fin += __shfl_xor_sync(FULL, fin, o);
    if (l == 0) {
        float logZ = __logf(fin) + shift + (float)ksum * 0.69314718055994531f;
        g_partial[b] = logZ - num;
    }
}

__global__ void crf_reduce(float* __restrict__ out) {
    __shared__ float s[256];
    int tid = threadIdx.x;
    s[tid] = g_partial[tid] + g_partial[tid + 256];
    __syncthreads();
    #pragma unroll
    for (int o = 128; o > 0; o >>= 1) {
        if (tid < o) s[tid] += s[tid + o];
        __syncthreads();
    }
    if (tid == 0) out[0] = s[0] * (1.0f / (float)BB);
}

extern "C" void kernel_launch(void* const* d_in, const int* in_sizes, int n_in,
                              void* d_out, int out_size) {
    const float*         em   = (const float*)d_in[0];
    const int*           tags = (const int*)d_in[1];
    const unsigned char* mask = (const unsigned char*)d_in[2];
    const float*         st   = (const float*)d_in[3];
    const float*         en   = (const float*)d_in[4];
    const float*         tr   = (const float*)d_in[5];
    crf_main<<<BB / 4, 128>>>(em, tags, mask, st, en, tr);
    crf_reduce<<<1, 256>>>((float*)d_out);
}

// round 10
// speedup vs baseline: 2.2558x; 2.2558x over previous
#include <cuda_runtime.h>
#include <stdint.h>

#define BB 512
#define SS 1024
#define TT 48

__device__ float g_partial[BB];

__device__ __forceinline__ unsigned long long pk2(float x, float y) {
    unsigned long long r;
    asm("mov.b64 %0, {%1,%2};" : "=l"(r) : "f"(x), "f"(y));
    return r;
}
__device__ __forceinline__ void upk2(unsigned long long v, float& x, float& y) {
    asm("mov.b64 {%0,%1}, %2;" : "=f"(x), "=f"(y) : "l"(v));
}
__device__ __forceinline__ unsigned long long fma2(unsigned long long a, unsigned long long b, unsigned long long c) {
    unsigned long long d;
    asm("fma.rn.f32x2 %0, %1, %2, %3;" : "=l"(d) : "l"(a), "l"(b), "l"(c));
    return d;
}
__device__ __forceinline__ unsigned long long add2(unsigned long long a, unsigned long long b) {
    unsigned long long d;
    asm("add.rn.f32x2 %0, %1, %2;" : "=l"(d) : "l"(a), "l"(b));
    return d;
}

// One warp per sequence, 4 warps/CTA (one per SMSP), 128 CTAs (1/SM).
// R3 layout: lane l owns col l (pA) and col 32+(l&15) (pB, lanes 0-15 live).
// Numerator+len: parallel prologue. Rescale: exponent of p_{t-1}[0] taken from
// the smem word every lane loads anyway -> branchless, no shfl, no divergence.
__global__ __launch_bounds__(128, 1) void crf_main(
    const float* __restrict__ em,          // [B,S,T]
    const int* __restrict__ tags,          // [B,S]
    const unsigned char* __restrict__ mask,// [B,S] bool OR int32 (auto-detected)
    const float* __restrict__ startT,      // [T]
    const float* __restrict__ endT,        // [T]
    const float* __restrict__ trans)       // [T,T]
{
    __shared__ __align__(16) float sP[4][2][TT];

    const unsigned FULL = 0xffffffffu;
    int tid = threadIdx.x;
    int w   = tid >> 5;
    int l   = tid & 31;
    int b   = blockIdx.x * 4 + w;

    bool isbool = ((mask[1] | mask[1025] | mask[2049] | mask[3073]) != 0);

    const float* embT = em + (size_t)b * SS * TT;
    const int*   tgT  = tags + (size_t)b * SS;

    // ===== parallel prologue: gold-path numerator + length (32 t's/lane) ====
    float num = 0.f;
    int cnt = 0;
    #pragma unroll 4
    for (int k = 0; k < 32; k++) {
        int t = l + 32 * k;
        int mk = isbool ? (int)mask[(size_t)b * SS + t]
                        : ((const int*)mask)[(size_t)b * SS + t];
        int tg = tgT[t];
        if (t == 0) {
            num += startT[tg] + embT[tg];
        } else {
            int tgm = tgT[t - 1];
            float cval = trans[tgm * TT + tg] + embT[t * TT + tg];
            num += mk ? cval : 0.f;
        }
        cnt += mk ? 1 : 0;
    }
    #pragma unroll
    for (int o = 16; o; o >>= 1) {
        num += __shfl_xor_sync(FULL, num, o);
        cnt += __shfl_xor_sync(FULL, cnt, o);
    }
    int len = cnt;
    if (len < 1) len = 1;
    if (len > SS) len = SS;
    num += endT[tgT[len - 1]];           // uniform across lanes

    // ===== this lane's two output columns =====
    int jA = l;
    int jB = 32 + (l & 15);

    // ===== E = exp(transitions) columns in registers (f32x2 pairs) =====
    unsigned long long colA[24], colB[24];
    #pragma unroll
    for (int m = 0; m < 24; m++) {
        colA[m] = pk2(__expf(trans[(2 * m) * TT + jA]),
                      __expf(trans[(2 * m + 1) * TT + jA]));
        colB[m] = pk2(__expf(trans[(2 * m) * TT + jB]),
                      __expf(trans[(2 * m + 1) * TT + jB]));
    }

    // ===== init p0 = exp(start + emit0 - shift) =====
    float sA0 = startT[jA] + embT[jA];
    float sB0 = startT[jB] + embT[jB];
    float shift = __shfl_sync(FULL, sA0, 0);
    sP[w][0][l] = __expf(sA0 - shift);
    if (l < 16) sP[w][0][32 + l] = __expf(sB0 - shift);
    __syncwarp();

    // ===== emission prefetch ring (depth 4) =====
    // row r lives at slot (r-1)&3
    float bufA[4], bufB[4];
    #pragma unroll
    for (int u = 0; u < 4; u++) {
        bufA[u] = embT[(1 + u) * TT + jA];
        bufB[u] = embT[(1 + u) * TT + jB];
    }

    int ksum = 0;

    // ---- one recurrence step (branchless, uniform) ----
    #define CRF_STEP(t, idx)                                                   \
    {                                                                          \
        float wA = __expf(bufA[idx]);                                          \
        float wB = __expf(bufB[idx]);                                          \
        int tp = (t) + 4; if (tp > SS - 1) tp = SS - 1;                        \
        bufA[idx] = embT[tp * TT + jA];                                        \
        bufB[idx] = embT[tp * TT + jB];                                        \
        int rb = ((t) + 1) & 1, wb = (t) & 1;                                  \
        const ulonglong2* sp =                                                 \
            reinterpret_cast<const ulonglong2*>(&sP[w][rb][0]);                \
        ulonglong2 v0 = sp[0];                                                 \
        float p00, p01;                                                        \
        upk2(v0.x, p00, p01);                                                  \
        unsigned eb = (__float_as_uint(p00) >> 23) & 255u;                     \
        if (eb < 64u) eb = 64u;                                                \
        if (eb > 190u) eb = 190u;                                              \
        int kk = (int)eb - 127;                                                \
        float Mf = __uint_as_float((unsigned)(127 - kk) << 23);                \
        ksum += kk;                                                            \
        wA *= Mf; wB *= Mf;                                                    \
        unsigned long long a0 = 0, a1 = 0, c0 = 0, c1 = 0;                     \
        a0 = fma2(v0.x, colA[0], a0);                                          \
        c0 = fma2(v0.x, colB[0], c0);                                          \
        a1 = fma2(v0.y, colA[1], a1);                                          \
        c1 = fma2(v0.y, colB[1], c1);                                          \
        _Pragma("unroll")                                                      \
        for (int q = 1; q < 12; q++) {                                         \
            ulonglong2 v = sp[q];                                              \
            a0 = fma2(v.x, colA[2 * q], a0);                                   \
            c0 = fma2(v.x, colB[2 * q], c0);                                   \
            a1 = fma2(v.y, colA[2 * q + 1], a1);                               \
            c1 = fma2(v.y, colB[2 * q + 1], c1);                               \
        }                                                                      \
        float xA, yA, xB, yB;                                                  \
        upk2(add2(a0, a1), xA, yA);                                            \
        upk2(add2(c0, c1), xB, yB);                                            \
        float pA = (xA + yA) * wA;                                             \
        float pB = (xB + yB) * wB;                                             \
        sP[w][wb][l] = pA;                                                     \
        if (l < 16) sP[w][wb][32 + l] = pB;                                    \
        __syncwarp();                                                          \
    }

    int t = 1;
    // full quads, no per-step guards (t0 == 1 mod 4 so slot == u)
    for (; t + 3 < len; t += 4) {
        CRF_STEP(t + 0, 0)
        CRF_STEP(t + 1, 1)
        CRF_STEP(t + 2, 2)
        CRF_STEP(t + 3, 3)
    }
    // remainder (0-3 steps), slot = (t-1)&3
    for (; t < len; t++) {
        int idx = (t - 1) & 3;
        CRF_STEP(t, idx)
    }
    #undef CRF_STEP

    // ===== finalize: logZ = log(sum_j p_j e^{end_j}) + shift + ksum*ln2 =====
    int fb = (len - 1) & 1;
    float fin = sP[w][fb][jA] * __expf(endT[jA]);
    if (l < 16) fin += sP[w][fb][jB] * __expf(endT[jB]);
    #pragma unroll
    for (int o = 16; o; o >>= 1) fin += __shfl_xor_sync(FULL, fin, o);
    if (l == 0) {
        float logZ = __logf(fin) + shift + (float)ksum * 0.69314718055994531f;
        g_partial[b] = logZ - num;
    }
}

__global__ void crf_reduce(float* __restrict__ out) {
    __shared__ float s[256];
    int tid = threadIdx.x;
    s[tid] = g_partial[tid] + g_partial[tid + 256];
    __syncthreads();
    #pragma unroll
    for (int o = 128; o > 0; o >>= 1) {
        if (tid < o) s[tid] += s[tid + o];
        __syncthreads();
    }
    if (tid == 0) out[0] = s[0] * (1.0f / (float)BB);
}

extern "C" void kernel_launch(void* const* d_in, const int* in_sizes, int n_in,
                              void* d_out, int out_size) {
    const float*         em   = (const float*)d_in[0];
    const int*           tags = (const int*)d_in[1];
    const unsigned char* mask = (const unsigned char*)d_in[2];
    const float*         st   = (const float*)d_in[3];
    const float*         en   = (const float*)d_in[4];
    const float*         tr   = (const float*)d_in[5];
    crf_main<<<BB / 4, 128>>>(em, tags, mask, st, en, tr);
    crf_reduce<<<1, 256>>>((float*)d_out);
}